// round 15
// baseline (speedup 1.0000x reference)
#include <cuda_runtime.h>
#include <math.h>

// ---------------- scratch (device globals; no allocation allowed) ----------------
__device__ float g_c1[24*32*32*32];   // conv1 out [img][32][32][32]
__device__ float g_c2[24*48*16*16];   // conv2 out [img][48][16][16]
__device__ float g_c3[24*64*8*8];     // conv3 out [img][64][8][8]
__device__ float g_logits[24*64];
__device__ float g_u[24*64*128];      // u[img][p][k]
__device__ float g_v[24*64*128];      // v[img][q][k] (includes bg1)
__device__ float g_score[144];        // score[b][j][i]

// ---------------- f32x2 packed helpers (sm_103a FFMA2 path) ----------------
__device__ __forceinline__ void unpack2(unsigned long long v, float& lo, float& hi) {
    asm("mov.b64 {%0, %1}, %2;" : "=f"(lo), "=f"(hi) : "l"(v));
}
__device__ __forceinline__ unsigned long long fma2(unsigned long long a,
                                                   unsigned long long b,
                                                   unsigned long long c) {
    unsigned long long d;
    asm("fma.rn.f32x2 %0, %1, %2, %3;" : "=l"(d) : "l"(a), "l"(b), "l"(c));
    return d;
}

// ---------------- conv1: 3->32, 64x64 -> 32x32, stride 2, pad (0,1) ----------------
__global__ void conv1_k(const float* __restrict__ sx, const float* __restrict__ qx,
                        const float* __restrict__ w, const float* __restrict__ bias) {
    __shared__ float ws[27];
    int o = blockIdx.x * 256 + threadIdx.x;
    int ch = (o >> 10) & 31, img = o >> 15;
    if (threadIdx.x < 27) ws[threadIdx.x] = w[ch*27 + threadIdx.x];
    __syncthreads();
    int x = o & 31, y = (o >> 5) & 31;
    int b = img / 6, s = img - b * 6;
    const float* base = (s < 5) ? sx + (size_t)((b*5 + s)*3) * 4096
                                : qx + (size_t)(b*3) * 4096;
    float acc = bias[ch];
    #pragma unroll
    for (int c = 0; c < 3; c++) {
        const float* in = base + c * 4096;
        const float* wp = ws + c * 9;
        #pragma unroll
        for (int kh = 0; kh < 3; kh++) {
            int iy = 2*y + kh; if (iy >= 64) continue;
            #pragma unroll
            for (int kw = 0; kw < 3; kw++) {
                int ix = 2*x + kw; if (ix >= 64) continue;
                acc += in[iy*64 + ix] * wp[kh*3 + kw];
            }
        }
    }
    g_c1[o] = fmaxf(acc, 0.f);
}

// ---------------- conv2: 32->48, 32x32 -> 16x16 ----------------
__global__ void conv2_k(const float* __restrict__ w, const float* __restrict__ bias) {
    __shared__ float ws[288];
    int blk = blockIdx.x;              // 0..1151 = img*48 + ch
    int ch = blk % 48, img = blk / 48;
    for (int i = threadIdx.x; i < 288; i += 256) ws[i] = w[ch*288 + i];
    __syncthreads();
    int o = blk * 256 + threadIdx.x;
    int x = o & 15, y = (o >> 4) & 15;
    float acc = bias[ch];
    const float* inb = g_c1 + (size_t)img * 32768;
    for (int c = 0; c < 32; c++) {
        const float* in = inb + c * 1024;
        const float* wp = ws + c * 9;
        #pragma unroll
        for (int kh = 0; kh < 3; kh++) {
            int iy = 2*y + kh; if (iy >= 32) continue;
            #pragma unroll
            for (int kw = 0; kw < 3; kw++) {
                int ix = 2*x + kw; if (ix >= 32) continue;
                acc += in[iy*32 + ix] * wp[kh*3 + kw];
            }
        }
    }
    g_c2[o] = fmaxf(acc, 0.f);
}

// ---------------- conv3: 48->64, 16x16 -> 8x8 ----------------
__global__ void conv3_k(const float* __restrict__ w, const float* __restrict__ bias) {
    __shared__ float ws[1728];
    int blk = blockIdx.x;              // 0..383
    int img = blk >> 4;
    int chb = (blk & 15) * 4;
    for (int i = threadIdx.x; i < 1728; i += 256) ws[i] = w[chb*432 + i];
    __syncthreads();
    int o = blk * 256 + threadIdx.x;
    int x = o & 7, y = (o >> 3) & 7, ch = (o >> 6) & 63;
    float acc = bias[ch];
    const float* inb = g_c2 + (size_t)img * 12288;
    const float* wb  = ws + (ch - chb) * 432;
    for (int c = 0; c < 48; c++) {
        const float* in = inb + c * 256;
        const float* wp = wb + c * 9;
        #pragma unroll
        for (int kh = 0; kh < 3; kh++) {
            int iy = 2*y + kh; if (iy >= 16) continue;
            #pragma unroll
            for (int kw = 0; kw < 3; kw++) {
                int ix = 2*x + kw; if (ix >= 16) continue;
                acc += in[iy*16 + ix] * wp[kh*3 + kw];
            }
        }
    }
    g_c3[o] = fmaxf(acc, 0.f);
}

// ---------------- fused uv + poollog ----------------
__global__ void uvpool_k(const float* __restrict__ Wg1, const float* __restrict__ bg1,
                         const float* __restrict__ Wlog, const float* __restrict__ blog) {
    int blk = blockIdx.x;
    int tid = threadIdx.x;
    if (blk < 1536) {
        __shared__ float a[66];
        int img = blk >> 6;
        int p   = blk & 63;
        if (tid < 64) a[tid] = g_c3[(size_t)img*4096 + tid*64 + p];
        if (tid == 64) a[64] = (float)(p >> 3) * 0.125f;   // ii[py]
        if (tid == 65) a[65] = (float)(p & 7)  * 0.125f;   // ii[px]
        __syncthreads();
        int n = tid & 127;
        bool isv = tid >= 128;
        const float* Wbase = Wg1 + (isv ? 66*128 : 0);
        float acc = isv ? bg1[n] : 0.f;
        #pragma unroll 6
        for (int c = 0; c < 66; c++) acc = fmaf(a[c], Wbase[c*128 + n], acc);
        size_t off = (size_t)img * 8192 + p * 128 + n;
        if (isv) g_v[off] = acc; else g_u[off] = acc;
    } else {
        __shared__ float pooled[64];
        int img = blk - 1536;
        int ch = tid >> 2, part = tid & 3;
        const float* fp = g_c3 + (size_t)img * 4096 + ch * 64 + part * 16;
        float s = 0.f;
        #pragma unroll
        for (int i = 0; i < 16; i++) s += fp[i];
        s += __shfl_xor_sync(0xffffffff, s, 1);
        s += __shfl_xor_sync(0xffffffff, s, 2);
        if (part == 0) pooled[ch] = s * (1.f / 64.f);
        __syncthreads();
        if (tid < 64) {
            float l = blog[tid];
            #pragma unroll 8
            for (int cc = 0; cc < 64; cc++) l = fmaf(pooled[cc], Wlog[cc*64 + tid], l);
            g_logits[img*64 + tid] = l;
        }
    }
}

// ---------------- pair kernel: 8q x 4n register tile, 128-row H phases ----------------
// One CTA per (b,j,i), 256 threads.
// smem (floats): U[64][132]=8448, Vs[64][132]=8448, Wp[64n][130]=8320 (k-major,
// bank-pad), H[128][132]=16896, bg2s[64], xfs[64], t1s[16].  ~170 KB.
// Phase = 2 p values (128 rows = pl*64 + q). 32 phases.
// GEMM thread tile: rows r0..r0+7 (rg=tid>>4), n = ng + 16*ni (ng=tid&15).
// FFMA2 lanes packed over (k even, k odd).
#define US 132
#define WS 130
__global__ void __launch_bounds__(256, 1) pair_k(
    const float* __restrict__ Wg2, const float* __restrict__ bg2,
    const float* __restrict__ Wf1, const float* __restrict__ bf1,
    const float* __restrict__ Wf2, const float* __restrict__ bf2) {
    extern __shared__ float sm[];
    float* U    = sm;                     // 8448
    float* Vs   = sm + 8448;              // 8448
    float* Wp   = sm + 16896;             // 8320
    float* H    = sm + 25216;             // 16896
    float* bg2s = sm + 42112;             // 64
    float* xfs  = sm + 42176;             // 64
    float* t1s  = sm + 42240;             // 16

    int tid = threadIdx.x;
    int blk = blockIdx.x;
    int b = blk / 36; int r = blk - b*36; int j = r / 6; int i = r - j*6;
    const float* up = g_u + (size_t)(b*6 + i) * 8192;
    const float* vp = g_v + (size_t)(b*6 + j) * 8192;

    for (int idx = tid; idx < 8192; idx += 256) {
        int row = idx >> 7, k = idx & 127;
        U[row*US + k]  = up[idx];
        Vs[row*US + k] = vp[idx];
        int n = idx & 63, kk = idx >> 6;  // Wg2 natural [k][n]
        Wp[n*WS + kk] = Wg2[idx];
    }
    if (tid < 64) bg2s[tid] = bg2[tid];
    __syncthreads();

    // GEMM mapping
    int ng = tid & 15, rg = tid >> 4;
    int r0 = rg * 8;
    float bb[4];
    #pragma unroll
    for (int ni = 0; ni < 4; ni++) bb[ni] = bg2s[ng + 16*ni];

    // build mapping: thread builds half a row (64 floats)
    int rb = tid >> 1, half = tid & 1;
    int pl = rb >> 6, qv = rb & 63;
    const float4* vrow = (const float4*)(Vs + qv*US) + half*16;
    float4* hrow = (float4*)(H + rb*US) + half*16;

    float run[32];
    #pragma unroll
    for (int t = 0; t < 32; t++) run[t] = 0.f;

    const ulonglong2* H2 = (const ulonglong2*)H;               // row = 33 ulonglong2
    const unsigned long long* W64 = (const unsigned long long*)Wp;  // row = 65 ull

    for (int pp = 0; pp < 64; pp += 2) {
        // ---- build H[128 rows][128 k] = relu(u_{pp+pl} + v_q) ----
        const float4* urow = (const float4*)(U + (pp + pl)*US) + half*16;
        #pragma unroll 8
        for (int t = 0; t < 16; t++) {
            float4 u4 = urow[t];
            float4 v4 = vrow[t];
            float4 h4;
            h4.x = fmaxf(u4.x + v4.x, 0.f);
            h4.y = fmaxf(u4.y + v4.y, 0.f);
            h4.z = fmaxf(u4.z + v4.z, 0.f);
            h4.w = fmaxf(u4.w + v4.w, 0.f);
            hrow[t] = h4;
        }
        __syncthreads();

        // ---- GEMM: 8 rows x 4 n, K=128 ----
        unsigned long long acc[8][4];
        #pragma unroll
        for (int qi = 0; qi < 8; qi++)
            #pragma unroll
            for (int ni = 0; ni < 4; ni++) acc[qi][ni] = 0ull;

        #pragma unroll 4
        for (int k4 = 0; k4 < 32; k4++) {
            ulonglong2 h[8];
            #pragma unroll
            for (int qi = 0; qi < 8; qi++) h[qi] = H2[(r0 + qi)*33 + k4];
            #pragma unroll
            for (int ni = 0; ni < 4; ni++) {
                int n = ng + 16*ni;
                unsigned long long w01 = W64[n*65 + 2*k4];
                unsigned long long w23 = W64[n*65 + 2*k4 + 1];
                #pragma unroll
                for (int qi = 0; qi < 8; qi++) {
                    acc[qi][ni] = fma2(h[qi].x, w01, acc[qi][ni]);
                    acc[qi][ni] = fma2(h[qi].y, w23, acc[qi][ni]);
                }
            }
        }
        // ---- bias + relu + running sum (registers only) ----
        #pragma unroll
        for (int qi = 0; qi < 8; qi++)
            #pragma unroll
            for (int ni = 0; ni < 4; ni++) {
                float e0, e1;
                unpack2(acc[qi][ni], e0, e1);
                run[qi*4 + ni] += fmaxf((e0 + e1) + bb[ni], 0.f);
            }
        __syncthreads();     // H free for next phase
    }

    // ---- reduce run -> x_f[64] via red[n][128 slots] (reuse H) ----
    float* red = H;
    {
        int hi = rg >> 3, qb = (rg & 7) * 8;
        #pragma unroll
        for (int qi = 0; qi < 8; qi++)
            #pragma unroll
            for (int ni = 0; ni < 4; ni++)
                red[(ng + 16*ni)*129 + (qb + qi)*2 + hi] = run[qi*4 + ni];
    }
    __syncthreads();
    if (tid < 64) {
        float s = 0.f;
        const float* rp = red + tid*129;
        #pragma unroll 8
        for (int t2 = 0; t2 < 128; t2++) s += rp[t2];
        xfs[tid] = s;
    }
    __syncthreads();
    if (tid < 16) {
        float s = bf1[tid];
        for (int c = 0; c < 64; c++) s = fmaf(xfs[c], Wf1[c*16 + tid], s);
        t1s[tid] = fmaxf(s, 0.f);
    }
    __syncthreads();
    if (tid == 0) {
        float s = bf2[0];
        for (int t2 = 0; t2 < 16; t2++) s = fmaf(t1s[t2], Wf2[t2], s);
        g_score[blk] = 1.f / (1.f + __expf(-s));
    }
}

// ---------------- final losses: single block ----------------
__global__ void final_k(const int* __restrict__ sy, const int* __restrict__ qy,
                        float* __restrict__ out) {
    __shared__ float sP[144], sY[144], scls[24];
    __shared__ int slab[24];
    int tid = threadIdx.x;
    if (tid < 144) sP[tid] = g_score[tid];
    if (tid < 24) {
        int b = tid / 6, s = tid - b*6;
        slab[tid] = (s < 5) ? sy[b*5 + s] : qy[b];
    }
    __syncthreads();
    if (tid < 24) {
        const float* row = g_logits + tid*64;
        float m = row[0];
        for (int n = 1; n < 64; n++) m = fmaxf(m, row[n]);
        float se = 0.f;
        for (int n = 0; n < 64; n++) se += __expf(row[n] - m);
        float lse = m + __logf(se);
        scls[tid] = -(row[slab[tid]] - lse);
    }
    if (tid < 144) {
        int b = tid / 36, r = tid - b*36; int jj = r / 6, ii = r - jj*6;
        sY[tid] = (slab[b*6 + jj] == slab[b*6 + ii]) ? 1.f : 0.f;
    }
    __syncthreads();
    if (tid == 0) {
        float cls = 0.f;
        for (int r2 = 0; r2 < 24; r2++) cls += scls[r2];
        cls /= 24.f;
        float euc = 0.f;
        for (int t = 0; t < 144; t++) { float d = sP[t] - sY[t]; euc += d*d; }
        euc /= 144.f;
        float syml = 0.f;
        for (int b2 = 0; b2 < 4; b2++) {
            float s2 = 0.f, a2 = 0.f;
            for (int jj = 0; jj < 6; jj++)
                for (int ii = 0; ii < 6; ii++) {
                    float pa = sP[b2*36 + jj*6 + ii];
                    float pb = sP[b2*36 + ii*6 + jj];
                    float sv = 0.5f*(pa + pb), av = 0.5f*(pa - pb);
                    s2 += sv*sv; a2 += av*av;
                }
            float sn = sqrtf(s2), an = sqrtf(a2);
            syml += (sn - an) / (sn + an);
        }
        syml *= 0.25f;
        out[0] = cls;
        out[1] = euc - 0.1f * syml;
        out[2] = syml;
    }
}

// ---------------- launch ----------------
extern "C" void kernel_launch(void* const* d_in, const int* in_sizes, int n_in,
                              void* d_out, int out_size) {
    const float* sx   = (const float*)d_in[0];
    const int*   sy   = (const int*)  d_in[1];
    const float* qx   = (const float*)d_in[2];
    const int*   qy   = (const int*)  d_in[3];
    const float* k1   = (const float*)d_in[4];
    const float* bc1  = (const float*)d_in[5];
    const float* k2   = (const float*)d_in[6];
    const float* bc2  = (const float*)d_in[7];
    const float* k3   = (const float*)d_in[8];
    const float* bc3  = (const float*)d_in[9];
    const float* Wlog = (const float*)d_in[10];
    const float* blog = (const float*)d_in[11];
    const float* Wg1  = (const float*)d_in[12];
    const float* bg1  = (const float*)d_in[13];
    const float* Wg2  = (const float*)d_in[14];
    const float* bg2  = (const float*)d_in[15];
    const float* Wf1  = (const float*)d_in[16];
    const float* bf1  = (const float*)d_in[17];
    const float* Wf2  = (const float*)d_in[18];
    const float* bf2  = (const float*)d_in[19];
    float* out = (float*)d_out;

    const int pair_smem = (42240 + 16 + 16) * sizeof(float); // ~169 KB
    cudaFuncSetAttribute(pair_k, cudaFuncAttributeMaxDynamicSharedMemorySize, pair_smem);

    conv1_k<<<3072, 256>>>(sx, qx, k1, bc1);
    conv2_k<<<1152, 256>>>(k2, bc2);
    conv3_k<<< 384, 256>>>(k3, bc3);
    uvpool_k<<<1560, 256>>>(Wg1, bg1, Wlog, blog);
    pair_k<<<144, 256, pair_smem>>>(Wg2, bg2, Wf1, bf1, Wf2, bf2);
    final_k<<<1, 160>>>(sy, qy, out);
}